// round 1
// baseline (speedup 1.0000x reference)
#include <cuda_runtime.h>
#include <math.h>
#include <stdint.h>

#define H 128
#define EPS 1e-9f
#define M_MAX 50000
#define L_MAX 400000
#define MH_MAX (M_MAX * H)

// Scratch layout (floats):
// 12 * MH_MAX : Ah, Bx, Wfx, Ufh, Wix, Wox, Wcx, hhat, fpc, Uih, Uoh, Uch
// 2 * L_MAX   : e, xexp
// 2 * M_MAX   : segmax, segsum
__device__ float g_scratch[12 * (size_t)MH_MAX + 2 * (size_t)L_MAX + 2 * (size_t)M_MAX];

__device__ __forceinline__ float sigmoidf(float x) { return 1.0f / (1.0f + expf(-x)); }

__device__ __forceinline__ void atomicMaxFloat(float* addr, float v) {
    if (v >= 0.0f) atomicMax((int*)addr, __float_as_int(v));
    else           atomicMin((unsigned int*)addr, __float_as_uint(v));
}

// ---------------------------------------------------------------------------
// init: zero hhat/fpc, segsum=0, segmax=-inf
// ---------------------------------------------------------------------------
__global__ void init_kernel(float* __restrict__ hhat, float* __restrict__ fpc,
                            float* __restrict__ segmax, float* __restrict__ segsum, int M) {
    int i = blockIdx.x * blockDim.x + threadIdx.x;
    int MH = M * H;
    if (i < MH) { hhat[i] = 0.0f; fpc[i] = 0.0f; }
    if (i < M)  { segmax[i] = __int_as_float(0xff800000); segsum[i] = 0.0f; }
}

// ---------------------------------------------------------------------------
// C[M,128] = A[M,128] @ W[128,128]^T (+ bias), fp32.
// Block: 128 rows x 128 cols. 256 threads, each 8x8 microtile.
// Shared tiles stored k-major with pad-129 (conflict-free loads & stores).
// ---------------------------------------------------------------------------
__global__ __launch_bounds__(256) void gemm_kernel(
    const float* __restrict__ A, const float* __restrict__ W,
    const float* __restrict__ bias, float* __restrict__ C, int M) {
    __shared__ float As[32][129];
    __shared__ float Ws[32][129];
    const int tid = threadIdx.x;
    const int tx = tid & 15;    // 0..15  -> cols tx + 16*c
    const int ty = tid >> 4;    // 0..15  -> rows ty*8 + r
    const int m0 = blockIdx.x * 128;

    float acc[8][8];
#pragma unroll
    for (int r = 0; r < 8; r++)
#pragma unroll
        for (int c = 0; c < 8; c++) acc[r][c] = 0.0f;

    for (int kc = 0; kc < H; kc += 32) {
#pragma unroll
        for (int i = tid; i < 128 * 32; i += 256) {
            int r = i >> 5, k = i & 31;     // per-warp: r fixed, k = lane -> coalesced
            int gm = m0 + r;
            As[k][r] = (gm < M) ? A[(size_t)gm * H + kc + k] : 0.0f;
            Ws[k][r] = W[(size_t)r * H + kc + k];
        }
        __syncthreads();
#pragma unroll
        for (int k = 0; k < 32; k++) {
            float a[8], w[8];
#pragma unroll
            for (int r = 0; r < 8; r++) a[r] = As[k][ty * 8 + r];   // broadcast
#pragma unroll
            for (int c = 0; c < 8; c++) w[c] = Ws[k][tx + 16 * c];  // conflict-free
#pragma unroll
            for (int r = 0; r < 8; r++)
#pragma unroll
                for (int c = 0; c < 8; c++) acc[r][c] = fmaf(a[r], w[c], acc[r][c]);
        }
        __syncthreads();
    }
#pragma unroll
    for (int r = 0; r < 8; r++) {
        int gm = m0 + ty * 8 + r;
        if (gm < M) {
#pragma unroll
            for (int c = 0; c < 8; c++) {
                int n = tx + 16 * c;
                float b = bias ? __ldg(&bias[n]) : 0.0f;
                C[(size_t)gm * H + n] = acc[r][c] + b;
            }
        }
    }
}

// ---------------------------------------------------------------------------
// e[l] = tanh(Ah[chi] + Bx[ci]) . v ; segmax via atomic float-max. Warp/edge.
// ---------------------------------------------------------------------------
__global__ __launch_bounds__(256) void edge_e_kernel(
    const int* __restrict__ ci, const int* __restrict__ chi,
    const float* __restrict__ Ah, const float* __restrict__ Bx,
    const float* __restrict__ v, float* __restrict__ e,
    float* __restrict__ segmax, int L) {
    int w = (blockIdx.x * blockDim.x + threadIdx.x) >> 5;
    int lane = threadIdx.x & 31;
    if (w >= L) return;
    int c = __ldg(&ci[w]), ch = __ldg(&chi[w]);
    float4 a  = ((const float4*)(Ah + (size_t)ch * H))[lane];
    float4 b  = ((const float4*)(Bx + (size_t)c  * H))[lane];
    float4 vv = ((const float4*)v)[lane];
    float s = tanhf(a.x + b.x) * vv.x + tanhf(a.y + b.y) * vv.y
            + tanhf(a.z + b.z) * vv.z + tanhf(a.w + b.w) * vv.w;
#pragma unroll
    for (int o = 16; o > 0; o >>= 1) s += __shfl_xor_sync(0xffffffffu, s, o);
    if (lane == 0) {
        e[w] = s;
        atomicMaxFloat(&segmax[c], s);
    }
}

// ---------------------------------------------------------------------------
// xexp = exp(e - segmax[ci]); segsum += xexp. Thread/edge.
// ---------------------------------------------------------------------------
__global__ void edge_exp_kernel(const int* __restrict__ ci, const float* __restrict__ e,
                                const float* __restrict__ segmax, float* __restrict__ xexp,
                                float* __restrict__ segsum, int L) {
    int i = blockIdx.x * blockDim.x + threadIdx.x;
    if (i >= L) return;
    int c = ci[i];
    float xe = expf(e[i] - segmax[c]);
    xexp[i] = xe;
    atomicAdd(&segsum[c], xe);
}

// ---------------------------------------------------------------------------
// hhat[ci] += attn * child_h[chi];  fpc[ci] += sigmoid(Wfx[ci]+Ufh[chi]) * child_c[chi]
// Warp/edge, float4 gathers, scalar atomicAdd scatters.
// ---------------------------------------------------------------------------
__global__ __launch_bounds__(256) void edge_scatter_kernel(
    const int* __restrict__ ci, const int* __restrict__ chi,
    const float* __restrict__ xexp, const float* __restrict__ segsum,
    const float* __restrict__ child_h, const float* __restrict__ child_c,
    const float* __restrict__ Wfx, const float* __restrict__ Ufh,
    float* __restrict__ hhat, float* __restrict__ fpc, int L) {
    int w = (blockIdx.x * blockDim.x + threadIdx.x) >> 5;
    int lane = threadIdx.x & 31;
    if (w >= L) return;
    int c = __ldg(&ci[w]), ch = __ldg(&chi[w]);
    float attn = xexp[w] / (segsum[c] + EPS);
    float4 hv = ((const float4*)(child_h + (size_t)ch * H))[lane];
    float4 cv = ((const float4*)(child_c + (size_t)ch * H))[lane];
    float4 wf = ((const float4*)(Wfx + (size_t)c  * H))[lane];
    float4 uf = ((const float4*)(Ufh + (size_t)ch * H))[lane];
    float* hh = hhat + (size_t)c * H + lane * 4;
    float* fp = fpc  + (size_t)c * H + lane * 4;
    atomicAdd(hh + 0, attn * hv.x);
    atomicAdd(hh + 1, attn * hv.y);
    atomicAdd(hh + 2, attn * hv.z);
    atomicAdd(hh + 3, attn * hv.w);
    atomicAdd(fp + 0, sigmoidf(wf.x + uf.x) * cv.x);
    atomicAdd(fp + 1, sigmoidf(wf.y + uf.y) * cv.y);
    atomicAdd(fp + 2, sigmoidf(wf.z + uf.z) * cv.z);
    atomicAdd(fp + 3, sigmoidf(wf.w + uf.w) * cv.w);
}

// ---------------------------------------------------------------------------
// Final gates + outputs: out[0:MH]=h, out[MH:2MH]=c
// ---------------------------------------------------------------------------
__global__ void final_kernel(
    const float* __restrict__ Wix, const float* __restrict__ Uih,
    const float* __restrict__ Wox, const float* __restrict__ Uoh,
    const float* __restrict__ Wcx, const float* __restrict__ Uch,
    const float* __restrict__ fpc, float* __restrict__ out, int MH) {
    int i = blockIdx.x * blockDim.x + threadIdx.x;
    if (i >= MH) return;
    float iv = sigmoidf(Wix[i] + Uih[i]);
    float ct = tanhf(Wcx[i] + Uch[i]);
    float cc = fmaf(iv, ct, fpc[i]);
    float ov = sigmoidf(Wox[i] + Uoh[i]);
    out[i] = ov * tanhf(cc);
    out[MH + i] = cc;
}

// ---------------------------------------------------------------------------
extern "C" void kernel_launch(void* const* d_in, const int* in_sizes, int n_in,
                              void* d_out, int out_size) {
    const float* x_emb   = (const float*)d_in[0];
    const float* child_h = (const float*)d_in[1];
    const float* child_c = (const float*)d_in[2];
    const int*   ci      = (const int*)d_in[3];
    const int*   chi     = (const int*)d_in[4];
    const float* Wi_w = (const float*)d_in[5];
    const float* Ui_w = (const float*)d_in[6];
    const float* Wf_w = (const float*)d_in[7];
    const float* Uf_w = (const float*)d_in[8];
    const float* Wo_w = (const float*)d_in[9];
    const float* Uo_w = (const float*)d_in[10];
    const float* Wc_w = (const float*)d_in[11];
    const float* Uc_w = (const float*)d_in[12];
    const float* Wa_w = (const float*)d_in[13];
    const float* Ua_w = (const float*)d_in[14];
    const float* Wi_b = (const float*)d_in[15];
    const float* Wf_b = (const float*)d_in[16];
    const float* Wo_b = (const float*)d_in[17];
    const float* Wc_b = (const float*)d_in[18];
    const float* Wa_b = (const float*)d_in[19];
    const float* v_w  = (const float*)d_in[20];

    const int M  = in_sizes[0] / H;
    const int L  = in_sizes[3];
    const int MH = M * H;

    float* s = nullptr;
    cudaGetSymbolAddress((void**)&s, g_scratch);
    float* Ah   = s + 0  * (size_t)MH_MAX;
    float* Bx   = s + 1  * (size_t)MH_MAX;
    float* Wfx  = s + 2  * (size_t)MH_MAX;
    float* Ufh  = s + 3  * (size_t)MH_MAX;
    float* Wix  = s + 4  * (size_t)MH_MAX;
    float* Wox  = s + 5  * (size_t)MH_MAX;
    float* Wcx  = s + 6  * (size_t)MH_MAX;
    float* hhat = s + 7  * (size_t)MH_MAX;
    float* fpc  = s + 8  * (size_t)MH_MAX;
    float* Uih  = s + 9  * (size_t)MH_MAX;
    float* Uoh  = s + 10 * (size_t)MH_MAX;
    float* Uch  = s + 11 * (size_t)MH_MAX;
    float* e_v    = s + 12 * (size_t)MH_MAX;
    float* xexp   = e_v + L_MAX;
    float* segmax = xexp + L_MAX;
    float* segsum = segmax + M_MAX;

    const int gg = (M + 127) / 128;
    const int eb = (L + 7) / 8;      // warp-per-edge, 8 warps/block

    init_kernel<<<(MH + 255) / 256, 256>>>(hhat, fpc, segmax, segsum, M);

    // phase-1 GEMMs
    gemm_kernel<<<gg, 256>>>(child_h, Wa_w, Wa_b, Ah,  M);
    gemm_kernel<<<gg, 256>>>(x_emb,   Ua_w, nullptr, Bx, M);
    gemm_kernel<<<gg, 256>>>(x_emb,   Wf_w, Wf_b, Wfx, M);
    gemm_kernel<<<gg, 256>>>(child_h, Uf_w, nullptr, Ufh, M);
    gemm_kernel<<<gg, 256>>>(x_emb,   Wi_w, Wi_b, Wix, M);
    gemm_kernel<<<gg, 256>>>(x_emb,   Wo_w, Wo_b, Wox, M);
    gemm_kernel<<<gg, 256>>>(x_emb,   Wc_w, Wc_b, Wcx, M);

    // segment attention
    edge_e_kernel<<<eb, 256>>>(ci, chi, Ah, Bx, v_w, e_v, segmax, L);
    edge_exp_kernel<<<(L + 255) / 256, 256>>>(ci, e_v, segmax, xexp, segsum, L);
    edge_scatter_kernel<<<eb, 256>>>(ci, chi, xexp, segsum, child_h, child_c,
                                     Wfx, Ufh, hhat, fpc, L);

    // phase-2 GEMMs (h_hat)
    gemm_kernel<<<gg, 256>>>(hhat, Ui_w, nullptr, Uih, M);
    gemm_kernel<<<gg, 256>>>(hhat, Uo_w, nullptr, Uoh, M);
    gemm_kernel<<<gg, 256>>>(hhat, Uc_w, nullptr, Uch, M);

    final_kernel<<<(MH + 255) / 256, 256>>>(Wix, Uih, Wox, Uoh, Wcx, Uch, fpc,
                                            (float*)d_out, MH);
}

// round 3
// speedup vs baseline: 1.4183x; 1.4183x over previous
#include <cuda_runtime.h>
#include <math.h>
#include <stdint.h>

#define H 128
#define EPS 1e-9f
#define M_MAX 50000
#define L_MAX 400000
#define MH_MAX (M_MAX * H)

__device__ float g_scratch[12 * (size_t)MH_MAX + 2 * (size_t)L_MAX + 2 * (size_t)M_MAX];

__device__ __forceinline__ float sigmoidf(float x) { return 1.0f / (1.0f + expf(-x)); }

__device__ __forceinline__ void atomicMaxFloat(float* addr, float v) {
    if (v >= 0.0f) atomicMax((int*)addr, __float_as_int(v));
    else           atomicMin((unsigned int*)addr, __float_as_uint(v));
}

__device__ __forceinline__ uint32_t tf32_rna(float x) {
    uint32_t o;
    asm("cvt.rna.tf32.f32 %0, %1;" : "=r"(o) : "f"(x));
    return o;
}

// ===========================================================================
// Tensor-core GEMM via mma.sync tf32 (HMMA path, compute_103-safe PTX).
// C_w[M,128] = A[M,128] @ W_w[128,128]^T (+ b_w), up to 5 weights per launch
// sharing the staged A tile. Block: 128x128 tile, 256 thr = 8 warps (4m x 2n),
// warp tile 32x64, mma m16n8k8, 16 k-steps. smem rows padded to 132 u32.
// ===========================================================================
#define SMEM_LDA 132
#define GEMM_DSMEM (2 * 128 * SMEM_LDA * 4)

__device__ __forceinline__ void stage_tile_tf32(
    uint32_t* dst, const float* __restrict__ src, int rows_valid) {
    int tid = threadIdx.x;
#pragma unroll
    for (int i = tid; i < 128 * 32; i += 256) {
        int r = i >> 5, c4 = i & 31;
        float4 v = make_float4(0.f, 0.f, 0.f, 0.f);
        if (r < rows_valid) v = ((const float4*)(src + (size_t)r * H))[c4];
        uint4 u;
        u.x = tf32_rna(v.x); u.y = tf32_rna(v.y);
        u.z = tf32_rna(v.z); u.w = tf32_rna(v.w);
        *(uint4*)(dst + r * SMEM_LDA + c4 * 4) = u;
    }
}

__global__ __launch_bounds__(256, 1) void gemm_mma_kernel(
    const float* __restrict__ A, int M, int nW,
    const float* W0, const float* W1, const float* W2, const float* W3, const float* W4,
    const float* b0, const float* b1, const float* b2, const float* b3, const float* b4,
    float* C0, float* C1, float* C2, float* C3, float* C4) {
    extern __shared__ uint32_t sm[];
    uint32_t* As = sm;
    uint32_t* Ws = sm + 128 * SMEM_LDA;

    const float* Wp[5] = {W0, W1, W2, W3, W4};
    const float* bp[5] = {b0, b1, b2, b3, b4};
    float*       Cp[5] = {C0, C1, C2, C3, C4};

    const int tid = threadIdx.x;
    const int wid = tid >> 5, lane = tid & 31;
    const int wm = wid & 3, wn = wid >> 2;
    const int gid = lane >> 2, tig = lane & 3;
    const int m0 = blockIdx.x * 128;
    const int rows = min(128, M - m0);

    stage_tile_tf32(As, A + (size_t)m0 * H, rows);

    const int rA = wm * 32 + gid;
    const int nB = wn * 64 + gid;

    for (int w = 0; w < nW; w++) {
        __syncthreads();
        stage_tile_tf32(Ws, Wp[w], 128);
        __syncthreads();

        float acc[2][8][4];
#pragma unroll
        for (int mt = 0; mt < 2; mt++)
#pragma unroll
            for (int nt = 0; nt < 8; nt++)
#pragma unroll
                for (int j = 0; j < 4; j++) acc[mt][nt][j] = 0.0f;

#pragma unroll
        for (int ks = 0; ks < 16; ks++) {
            const int k0 = ks * 8;
            uint32_t a[2][4], b[8][2];
#pragma unroll
            for (int mt = 0; mt < 2; mt++) {
                int r0 = rA + mt * 16;
                a[mt][0] = As[r0 * SMEM_LDA + k0 + tig];
                a[mt][1] = As[(r0 + 8) * SMEM_LDA + k0 + tig];
                a[mt][2] = As[r0 * SMEM_LDA + k0 + tig + 4];
                a[mt][3] = As[(r0 + 8) * SMEM_LDA + k0 + tig + 4];
            }
#pragma unroll
            for (int nt = 0; nt < 8; nt++) {
                int n = nB + nt * 8;
                b[nt][0] = Ws[n * SMEM_LDA + k0 + tig];
                b[nt][1] = Ws[n * SMEM_LDA + k0 + tig + 4];
            }
#pragma unroll
            for (int mt = 0; mt < 2; mt++)
#pragma unroll
                for (int nt = 0; nt < 8; nt++) {
                    asm volatile(
                        "mma.sync.aligned.m16n8k8.row.col.f32.tf32.tf32.f32 "
                        "{%0,%1,%2,%3}, {%4,%5,%6,%7}, {%8,%9}, {%0,%1,%2,%3};"
                        : "+f"(acc[mt][nt][0]), "+f"(acc[mt][nt][1]),
                          "+f"(acc[mt][nt][2]), "+f"(acc[mt][nt][3])
                        : "r"(a[mt][0]), "r"(a[mt][1]), "r"(a[mt][2]), "r"(a[mt][3]),
                          "r"(b[nt][0]), "r"(b[nt][1]));
                }
        }

        const float* bias = bp[w];
        float* C = Cp[w];
#pragma unroll
        for (int mt = 0; mt < 2; mt++) {
            int r0 = m0 + rA + mt * 16;
#pragma unroll
            for (int nt = 0; nt < 8; nt++) {
                int col = wn * 64 + nt * 8 + tig * 2;
                float bx = 0.f, by = 0.f;
                if (bias) { bx = __ldg(&bias[col]); by = __ldg(&bias[col + 1]); }
                if (r0 < M) {
                    float2 v = make_float2(acc[mt][nt][0] + bx, acc[mt][nt][1] + by);
                    *(float2*)(C + (size_t)r0 * H + col) = v;
                }
                if (r0 + 8 < M) {
                    float2 v = make_float2(acc[mt][nt][2] + bx, acc[mt][nt][3] + by);
                    *(float2*)(C + (size_t)(r0 + 8) * H + col) = v;
                }
            }
        }
    }
}

// ---------------------------------------------------------------------------
__global__ void init_kernel(float* __restrict__ hhat, float* __restrict__ fpc,
                            float* __restrict__ segmax, float* __restrict__ segsum, int M) {
    int i = blockIdx.x * blockDim.x + threadIdx.x;
    int MH = M * H;
    if (i < MH) { hhat[i] = 0.0f; fpc[i] = 0.0f; }
    if (i < M)  { segmax[i] = __int_as_float(0xff800000); segsum[i] = 0.0f; }
}

// ---------------------------------------------------------------------------
__global__ __launch_bounds__(256) void edge_e_kernel(
    const int* __restrict__ ci, const int* __restrict__ chi,
    const float* __restrict__ Ah, const float* __restrict__ Bx,
    const float* __restrict__ v, float* __restrict__ e,
    float* __restrict__ segmax, int L) {
    int w = (blockIdx.x * blockDim.x + threadIdx.x) >> 5;
    int lane = threadIdx.x & 31;
    if (w >= L) return;
    int c = __ldg(&ci[w]), ch = __ldg(&chi[w]);
    float4 a  = ((const float4*)(Ah + (size_t)ch * H))[lane];
    float4 b  = ((const float4*)(Bx + (size_t)c  * H))[lane];
    float4 vv = ((const float4*)v)[lane];
    float s = tanhf(a.x + b.x) * vv.x + tanhf(a.y + b.y) * vv.y
            + tanhf(a.z + b.z) * vv.z + tanhf(a.w + b.w) * vv.w;
#pragma unroll
    for (int o = 16; o > 0; o >>= 1) s += __shfl_xor_sync(0xffffffffu, s, o);
    if (lane == 0) {
        e[w] = s;
        atomicMaxFloat(&segmax[c], s);
    }
}

// ---------------------------------------------------------------------------
__global__ void edge_exp_kernel(const int* __restrict__ ci, const float* __restrict__ e,
                                const float* __restrict__ segmax, float* __restrict__ xexp,
                                float* __restrict__ segsum, int L) {
    int i = blockIdx.x * blockDim.x + threadIdx.x;
    if (i >= L) return;
    int c = ci[i];
    float xe = expf(e[i] - segmax[c]);
    xexp[i] = xe;
    atomicAdd(&segsum[c], xe);
}

// ---------------------------------------------------------------------------
__global__ __launch_bounds__(256) void edge_scatter_kernel(
    const int* __restrict__ ci, const int* __restrict__ chi,
    const float* __restrict__ xexp, const float* __restrict__ segsum,
    const float* __restrict__ child_h, const float* __restrict__ child_c,
    const float* __restrict__ Wfx, const float* __restrict__ Ufh,
    float* __restrict__ hhat, float* __restrict__ fpc, int L) {
    int w = (blockIdx.x * blockDim.x + threadIdx.x) >> 5;
    int lane = threadIdx.x & 31;
    if (w >= L) return;
    int c = __ldg(&ci[w]), ch = __ldg(&chi[w]);
    float attn = xexp[w] / (segsum[c] + EPS);
    float4 hv = ((const float4*)(child_h + (size_t)ch * H))[lane];
    float4 cv = ((const float4*)(child_c + (size_t)ch * H))[lane];
    float4 wf = ((const float4*)(Wfx + (size_t)c  * H))[lane];
    float4 uf = ((const float4*)(Ufh + (size_t)ch * H))[lane];
    float* hh = hhat + (size_t)c * H + lane * 4;
    float* fp = fpc  + (size_t)c * H + lane * 4;
    atomicAdd(hh + 0, attn * hv.x);
    atomicAdd(hh + 1, attn * hv.y);
    atomicAdd(hh + 2, attn * hv.z);
    atomicAdd(hh + 3, attn * hv.w);
    atomicAdd(fp + 0, sigmoidf(wf.x + uf.x) * cv.x);
    atomicAdd(fp + 1, sigmoidf(wf.y + uf.y) * cv.y);
    atomicAdd(fp + 2, sigmoidf(wf.z + uf.z) * cv.z);
    atomicAdd(fp + 3, sigmoidf(wf.w + uf.w) * cv.w);
}

// ---------------------------------------------------------------------------
__global__ void final_kernel(
    const float* __restrict__ Wix, const float* __restrict__ Uih,
    const float* __restrict__ Wox, const float* __restrict__ Uoh,
    const float* __restrict__ Wcx, const float* __restrict__ Uch,
    const float* __restrict__ fpc, float* __restrict__ out, int MH) {
    int i = blockIdx.x * blockDim.x + threadIdx.x;
    if (i >= MH) return;
    float iv = sigmoidf(Wix[i] + Uih[i]);
    float ct = tanhf(Wcx[i] + Uch[i]);
    float cc = fmaf(iv, ct, fpc[i]);
    float ov = sigmoidf(Wox[i] + Uoh[i]);
    out[i] = ov * tanhf(cc);
    out[MH + i] = cc;
}

// ---------------------------------------------------------------------------
extern "C" void kernel_launch(void* const* d_in, const int* in_sizes, int n_in,
                              void* d_out, int out_size) {
    const float* x_emb   = (const float*)d_in[0];
    const float* child_h = (const float*)d_in[1];
    const float* child_c = (const float*)d_in[2];
    const int*   ci      = (const int*)d_in[3];
    const int*   chi     = (const int*)d_in[4];
    const float* Wi_w = (const float*)d_in[5];
    const float* Ui_w = (const float*)d_in[6];
    const float* Wf_w = (const float*)d_in[7];
    const float* Uf_w = (const float*)d_in[8];
    const float* Wo_w = (const float*)d_in[9];
    const float* Uo_w = (const float*)d_in[10];
    const float* Wc_w = (const float*)d_in[11];
    const float* Uc_w = (const float*)d_in[12];
    const float* Wa_w = (const float*)d_in[13];
    const float* Ua_w = (const float*)d_in[14];
    const float* Wi_b = (const float*)d_in[15];
    const float* Wf_b = (const float*)d_in[16];
    const float* Wo_b = (const float*)d_in[17];
    const float* Wc_b = (const float*)d_in[18];
    const float* Wa_b = (const float*)d_in[19];
    const float* v_w  = (const float*)d_in[20];

    const int M  = in_sizes[0] / H;
    const int L  = in_sizes[3];
    const int MH = M * H;

    float* s = nullptr;
    cudaGetSymbolAddress((void**)&s, g_scratch);
    float* Ah   = s + 0  * (size_t)MH_MAX;
    float* Bx   = s + 1  * (size_t)MH_MAX;
    float* Wfx  = s + 2  * (size_t)MH_MAX;
    float* Ufh  = s + 3  * (size_t)MH_MAX;
    float* Wix  = s + 4  * (size_t)MH_MAX;
    float* Wox  = s + 5  * (size_t)MH_MAX;
    float* Wcx  = s + 6  * (size_t)MH_MAX;
    float* hhat = s + 7  * (size_t)MH_MAX;
    float* fpc  = s + 8  * (size_t)MH_MAX;
    float* Uih  = s + 9  * (size_t)MH_MAX;
    float* Uoh  = s + 10 * (size_t)MH_MAX;
    float* Uch  = s + 11 * (size_t)MH_MAX;
    float* e_v    = s + 12 * (size_t)MH_MAX;
    float* xexp   = e_v + L_MAX;
    float* segmax = xexp + L_MAX;
    float* segsum = segmax + M_MAX;

    cudaFuncSetAttribute(gemm_mma_kernel, cudaFuncAttributeMaxDynamicSharedMemorySize, GEMM_DSMEM);

    const int gg = (M + 127) / 128;
    const int eb = (L + 7) / 8;

    init_kernel<<<(MH + 255) / 256, 256>>>(hhat, fpc, segmax, segsum, M);

    gemm_mma_kernel<<<gg, 256, GEMM_DSMEM>>>(
        x_emb, M, 5,
        Wi_w, Wf_w, Wo_w, Wc_w, Ua_w,
        Wi_b, Wf_b, Wo_b, Wc_b, nullptr,
        Wix, Wfx, Wox, Wcx, Bx);

    gemm_mma_kernel<<<gg, 256, GEMM_DSMEM>>>(
        child_h, M, 2,
        Wa_w, Uf_w, nullptr, nullptr, nullptr,
        Wa_b, nullptr, nullptr, nullptr, nullptr,
        Ah, Ufh, nullptr, nullptr, nullptr);

    edge_e_kernel<<<eb, 256>>>(ci, chi, Ah, Bx, v_w, e_v, segmax, L);
    edge_exp_kernel<<<(L + 255) / 256, 256>>>(ci, e_v, segmax, xexp, segsum, L);
    edge_scatter_kernel<<<eb, 256>>>(ci, chi, xexp, segsum, child_h, child_c,
                                     Wfx, Ufh, hhat, fpc, L);

    gemm_mma_kernel<<<gg, 256, GEMM_DSMEM>>>(
        hhat, M, 3,
        Ui_w, Uo_w, Uc_w, nullptr, nullptr,
        nullptr, nullptr, nullptr, nullptr, nullptr,
        Uih, Uoh, Uch, nullptr, nullptr);

    final_kernel<<<(MH + 255) / 256, 256>>>(Wix, Uih, Wox, Uoh, Wcx, Uch, fpc,
                                            (float*)d_out, MH);
}